// round 3
// baseline (speedup 1.0000x reference)
#include <cuda_runtime.h>

// SSIM 1-D loss, window 11, sigma 1.5, zero pad 5. B=16,C=32,T=48000 -> 512 rows.
// grid (24, 512), 128 threads/block, 16 outputs/thread (tile 2048).
// SMEM: one padded array of float4 (u, v, u^2, v^2), u=p+t, v=p-t.
// Conv: 26 sliding LDS.128 per thread, 352 fma.rn.f32x2 (2 FMA each).
// Invalid (zero-padded) outputs yield ssim==1 -> contribute 0, no predicate.
// Block partial -> g_part; last block (atomicInc) reduces + writes scalar.

#define TT     48000
#define NROWS  512
#define TILE   2048
#define TPB    128
#define RPT    16
#define NTILES 24
#define NBLK   (NTILES * NROWS)
#define NL     (TILE + 32)
#define SSZ    (NL + (NL >> 4) + 4)
#define C1F    1.0e-4f
#define C2F    9.0e-4f

__device__ float g_part[NBLK];
__device__ unsigned int g_cnt = 0;   // self-resetting via atomicInc wrap

__device__ __forceinline__ unsigned long long pk2(float lo, float hi) {
    unsigned long long r;
    asm("mov.b64 %0, {%1, %2};" : "=l"(r) : "f"(lo), "f"(hi));
    return r;
}
__device__ __forceinline__ void upk2(unsigned long long v, float& lo, float& hi) {
    asm("mov.b64 {%0, %1}, %2;" : "=f"(lo), "=f"(hi) : "l"(v));
}
__device__ __forceinline__ unsigned long long ffma2(unsigned long long a,
                                                    unsigned long long b,
                                                    unsigned long long c) {
    unsigned long long d;
    asm("fma.rn.f32x2 %0, %1, %2, %3;" : "=l"(d) : "l"(a), "l"(b), "l"(c));
    return d;
}

__global__ __launch_bounds__(TPB) void ssim_k(const float* __restrict__ pred,
                                              const float* __restrict__ tgt,
                                              float* __restrict__ out) {
    __shared__ float4 sbuf[SSZ];
    __shared__ float  wsum[TPB / 32];
    __shared__ double dsh[TPB / 32];
    __shared__ int    isLast;

    const int tid       = threadIdx.x;
    const int tile      = blockIdx.x;
    const int row       = blockIdx.y;
    const int rowBase   = row * TT;
    const int tileStart = tile * TILE;

    // ---- interior: 16 elems/thread, vectorized (TT % 16 == 0) ----
    {
        const int src0 = tileStart + tid * RPT;
        float p[RPT], t[RPT];
        if (src0 + RPT - 1 < TT) {
            const float4* pp = reinterpret_cast<const float4*>(pred + rowBase + src0);
            const float4* tp = reinterpret_cast<const float4*>(tgt  + rowBase + src0);
#pragma unroll
            for (int q = 0; q < 4; q++) {
                float4 a = pp[q], b = tp[q];
                p[4*q+0]=a.x; p[4*q+1]=a.y; p[4*q+2]=a.z; p[4*q+3]=a.w;
                t[4*q+0]=b.x; t[4*q+1]=b.y; t[4*q+2]=b.z; t[4*q+3]=b.w;
            }
        } else {
#pragma unroll
            for (int e = 0; e < RPT; e++) { p[e] = 0.f; t[e] = 0.f; }
        }
        // logical i0 = 16 + tid*16 (multiple of 16) -> phys = i + 1 + tid
        const int ph0 = 16 + tid * RPT + 1 + tid;
#pragma unroll
        for (int e = 0; e < RPT; e++) {
            float u = p[e] + t[e];
            float v = p[e] - t[e];
            unsigned long long uv = pk2(u, v);
            unsigned long long sq = ffma2(uv, uv, 0ull);
            float u2, v2; upk2(sq, u2, v2);
            sbuf[ph0 + e] = make_float4(u, v, u2, v2);
        }
    }
    // ---- halos (5 each side) ----
    if (tid < 5) {                       // left: logical i = 11+tid (phys == i)
        int src = tileStart - 5 + tid;
        float p = 0.f, t = 0.f;
        if (src >= 0) { p = pred[rowBase + src]; t = tgt[rowBase + src]; }
        float u = p + t, v = p - t;
        sbuf[11 + tid] = make_float4(u, v, u * u, v * v);
    } else if (tid >= 8 && tid < 13) {   // right: i = 2064+(tid-8), phys = i+129
        int h = tid - 8;
        int src = tileStart + TILE + h;
        float p = 0.f, t = 0.f;
        if (src < TT) { p = pred[rowBase + src]; t = tgt[rowBase + src]; }
        sbuf[2064 + h + 129] = make_float4(p + t, p - t,
                                           (p + t) * (p + t), (p - t) * (p - t));
    }
    __syncthreads();

    // ---- packed Gaussian weights ----
    const float Wv[11] = {
        0.001028380f, 0.007598758f, 0.036000773f, 0.109360755f, 0.213005542f,
        0.266011585f,
        0.213005542f, 0.109360755f, 0.036000773f, 0.007598758f, 0.001028380f
    };
    unsigned long long wp[11];
#pragma unroll
    for (int w = 0; w < 11; w++) wp[w] = pk2(Wv[w], Wv[w]);

    // ---- sliding-window conv: 26 LDS.128, 352 FFMA2 ----
    unsigned long long aUV[RPT], aPQ[RPT];
#pragma unroll
    for (int j = 0; j < RPT; j++) { aUV[j] = 0ull; aPQ[j] = 0ull; }

    const int s = tid * RPT + 11;        // first logical read index
#pragma unroll
    for (int k = 0; k < RPT + 10; k++) {
        int li = s + k;
        float4 q = sbuf[li + (li >> 4)];
        unsigned long long quv = pk2(q.x, q.y);
        unsigned long long qpq = pk2(q.z, q.w);
#pragma unroll
        for (int j = 0; j < RPT; j++) {
            int w = k - j;
            if (w >= 0 && w < 11) {
                aUV[j] = ffma2(quv, wp[w], aUV[j]);
                aPQ[j] = ffma2(qpq, wp[w], aPQ[j]);
            }
        }
    }

    // ---- epilogue: SSIM per output (no bounds check: padded -> ssim == 1) ----
    float lsum = 0.0f;
#pragma unroll
    for (int j = 0; j < RPT; j++) {
        float U, V, Pu, Pv;
        upk2(aUV[j], U, V);
        upk2(aPQ[j], Pu, Pv);
        float U2 = U * U;
        float V2 = V * V;
        float t1 = fmaf(0.5f, U2, C1F);
        float a2 = fmaf(-0.5f, V2, t1);                   // (U2-V2)/2 + C1
        float b2 = fmaf( 0.5f, V2, t1);                   // (U2+V2)/2 + C1
        float t2 = fmaf(0.5f, Pu, C2F);
        float t3 = fmaf(-0.5f, U2, t2);
        float c2 = fmaf(-0.5f, Pv, fmaf( 0.5f, V2, t3));  // (Cu-Cv)/2-(U2-V2)/2+C2
        float d2 = fmaf( 0.5f, Pv, fmaf(-0.5f, V2, t3));  // (Cu+Cv)/2-(U2+V2)/2+C2
        lsum += 1.0f - __fdividef(a2 * c2, b2 * d2);
    }

    // ---- block reduce ----
#pragma unroll
    for (int off = 16; off; off >>= 1)
        lsum += __shfl_down_sync(0xffffffffu, lsum, off);
    const int wid  = tid >> 5;
    const int lane = tid & 31;
    if (lane == 0) wsum[wid] = lsum;
    __syncthreads();

    const int bid = blockIdx.y * gridDim.x + blockIdx.x;
    if (tid < 32) {
        float v2 = (tid < TPB / 32) ? wsum[tid] : 0.0f;
#pragma unroll
        for (int off = 2; off; off >>= 1)
            v2 += __shfl_down_sync(0xffffffffu, v2, off);
        if (tid == 0) {
            g_part[bid] = v2;
            __threadfence();
            unsigned int old = atomicInc(&g_cnt, NBLK - 1u);
            isLast = (old == NBLK - 1u) ? 1 : 0;
        }
    }
    __syncthreads();

    // ---- last block reduces all partials ----
    if (isLast) {
        double ds = 0.0;
        for (int k = tid; k < NBLK; k += TPB)
            ds += (double)g_part[k];
#pragma unroll
        for (int off = 16; off; off >>= 1)
            ds += __shfl_down_sync(0xffffffffu, ds, off);
        if (lane == 0) dsh[wid] = ds;
        __syncthreads();
        if (tid == 0) {
            double tot = 0.0;
#pragma unroll
            for (int i = 0; i < TPB / 32; i++) tot += dsh[i];
            out[0] = (float)(tot / (double)((long long)NROWS * TT));
        }
    }
}

extern "C" void kernel_launch(void* const* d_in, const int* in_sizes, int n_in,
                              void* d_out, int out_size) {
    (void)in_sizes; (void)n_in; (void)out_size;
    const float* pred = (const float*)d_in[0];
    const float* tgt  = (const float*)d_in[1];
    dim3 grid(NTILES, NROWS);
    ssim_k<<<grid, TPB>>>(pred, tgt, (float*)d_out);
}

// round 4
// speedup vs baseline: 1.0500x; 1.0500x over previous
#include <cuda_runtime.h>

// SSIM 1-D loss, window 11, sigma 1.5, zero pad 5. B=16,C=32,T=48000 -> 512 rows.
// grid (24, 512), 256 threads/block, 8 outputs/thread (tile 2048).
// Single padded SMEM array of float4 (u, v, u^2, v^2), u=p+t, v=p-t.
// Conv: 18 sliding LDS.128 per thread, 22 fma.rn.f32x2 per output.
// Epilogue: sum ssim (predicated on validity), lsum = valid_count - sum.
// Block partial -> g_part; last block (atomicInc, self-resetting) reduces.

#define TT     48000
#define NROWS  512
#define TILE   2048
#define TPB    256
#define RPT    8
#define NTILES 24
#define NBLK   (NTILES * NROWS)
#define NL     (TILE + 16)                 // logical [tileStart-8, tileStart+TILE+8)
#define SSZ    (NL + (NL >> 3) + 2)        // pad: phys = i + (i>>3)
#define C1F    1.0e-4f
#define C2F    9.0e-4f
#define CCF    (C1F + C2F)

__device__ float g_part[NBLK];
__device__ unsigned int g_cnt = 0;         // self-resetting via atomicInc wrap

__device__ __forceinline__ unsigned long long pk2(float lo, float hi) {
    unsigned long long r;
    asm("mov.b64 %0, {%1, %2};" : "=l"(r) : "f"(lo), "f"(hi));
    return r;
}
__device__ __forceinline__ void upk2(unsigned long long v, float& lo, float& hi) {
    asm("mov.b64 {%0, %1}, %2;" : "=f"(lo), "=f"(hi) : "l"(v));
}
__device__ __forceinline__ unsigned long long ffma2(unsigned long long a,
                                                    unsigned long long b,
                                                    unsigned long long c) {
    unsigned long long d;
    asm("fma.rn.f32x2 %0, %1, %2, %3;" : "=l"(d) : "l"(a), "l"(b), "l"(c));
    return d;
}

__global__ __launch_bounds__(TPB) void ssim_k(const float* __restrict__ pred,
                                              const float* __restrict__ tgt,
                                              float* __restrict__ out) {
    __shared__ float4 sbuf[SSZ];
    __shared__ float  wsum[TPB / 32];
    __shared__ double dsh[TPB / 32];
    __shared__ int    isLast;

    const int tid       = threadIdx.x;
    const int tile      = blockIdx.x;
    const int row       = blockIdx.y;
    const int rowBase   = row * TT;
    const int tileStart = tile * TILE;

    // ---- interior: 8 elems/thread, 2x float4 loads (TT % 8 == 0) ----
    {
        const int src0 = tileStart + tid * RPT;
        float p[RPT], t[RPT];
        if (src0 + RPT - 1 < TT) {
            const float4* pp = reinterpret_cast<const float4*>(pred + rowBase + src0);
            const float4* tp = reinterpret_cast<const float4*>(tgt  + rowBase + src0);
            float4 pa = pp[0], pb = pp[1];
            float4 ta = tp[0], tb = tp[1];
            p[0]=pa.x; p[1]=pa.y; p[2]=pa.z; p[3]=pa.w;
            p[4]=pb.x; p[5]=pb.y; p[6]=pb.z; p[7]=pb.w;
            t[0]=ta.x; t[1]=ta.y; t[2]=ta.z; t[3]=ta.w;
            t[4]=tb.x; t[5]=tb.y; t[6]=tb.z; t[7]=tb.w;
        } else {
#pragma unroll
            for (int e = 0; e < RPT; e++) { p[e] = 0.f; t[e] = 0.f; }
        }
        // logical i0 = 8 + tid*8 (multiple of 8) -> phys base = 9*(tid+1)
        const int ph0 = 9 * (tid + 1);
#pragma unroll
        for (int e = 0; e < RPT; e++) {
            float u = p[e] + t[e];
            float v = p[e] - t[e];
            unsigned long long sq = ffma2(pk2(u, v), pk2(u, v), 0ull);
            float u2, v2; upk2(sq, u2, v2);
            sbuf[ph0 + e] = make_float4(u, v, u2, v2);
        }
    }
    // ---- halos: logical 0..7 (phys == i) and 2056..2063 (phys = i+257) ----
    if (tid < 8) {
        int src = tileStart - 8 + tid;
        float p = 0.f, t = 0.f;
        if (src >= 0) { p = pred[rowBase + src]; t = tgt[rowBase + src]; }
        float u = p + t, v = p - t;
        sbuf[tid] = make_float4(u, v, u * u, v * v);
    } else if (tid >= 32 && tid < 40) {
        int h = tid - 32;
        int src = tileStart + TILE + h;
        float p = 0.f, t = 0.f;
        if (src < TT) { p = pred[rowBase + src]; t = tgt[rowBase + src]; }
        float u = p + t, v = p - t;
        sbuf[2056 + h + 257] = make_float4(u, v, u * u, v * v);
    }
    __syncthreads();

    // ---- packed Gaussian weights (constants -> ptxas can fold) ----
    const float Wv[11] = {
        0.001028380f, 0.007598758f, 0.036000773f, 0.109360755f, 0.213005542f,
        0.266011585f,
        0.213005542f, 0.109360755f, 0.036000773f, 0.007598758f, 0.001028380f
    };
    unsigned long long wp[11];
#pragma unroll
    for (int w = 0; w < 11; w++) wp[w] = pk2(Wv[w], Wv[w]);

    // ---- sliding-window conv: 18 LDS.128, 176 FFMA2 ----
    unsigned long long aUV[RPT], aPQ[RPT];
#pragma unroll
    for (int j = 0; j < RPT; j++) { aUV[j] = 0ull; aPQ[j] = 0ull; }

    const int s = tid * RPT + 3;               // first logical read index
#pragma unroll
    for (int k = 0; k < RPT + 10; k++) {
        int li = s + k;
        float4 q = sbuf[li + (li >> 3)];
        unsigned long long quv = pk2(q.x, q.y);
        unsigned long long qpq = pk2(q.z, q.w);
#pragma unroll
        for (int j = 0; j < RPT; j++) {
            int w = k - j;
            if (w >= 0 && w < 11) {
                aUV[j] = ffma2(quv, wp[w], aUV[j]);
                aPQ[j] = ffma2(qpq, wp[w], aPQ[j]);
            }
        }
    }

    // ---- epilogue: accumulate ssim (validity-predicated) ----
    float ssum = 0.0f;
    const int o0 = tileStart + tid * RPT;
#pragma unroll
    for (int j = 0; j < RPT; j++) {
        unsigned long long s2 = ffma2(aUV[j], aUV[j], 0ull);
        float U2, V2; upk2(s2, U2, V2);
        float Pu, Pv; upk2(aPQ[j], Pu, Pv);
        float t1 = fmaf(0.5f, U2, C1F);
        float a2 = fmaf(-0.5f, V2, t1);        // (U2-V2)/2 + C1
        float b2 = fmaf( 0.5f, V2, t1);        // (U2+V2)/2 + C1
        float c2 = fmaf(0.5f, Pu, fmaf(-0.5f, Pv, CCF - a2));
        float d2 = fmaf(0.5f, Pu, fmaf( 0.5f, Pv, CCF - b2));
        float ssim = __fdividef(a2 * c2, b2 * d2);
        if (o0 + j < TT) ssum += ssim;
    }
    // valid count for this thread (8 everywhere except end of last tile)
    int vc = TT - o0;
    vc = vc < 0 ? 0 : (vc > RPT ? RPT : vc);
    float lsum = (float)vc - ssum;

    // ---- block reduce ----
#pragma unroll
    for (int off = 16; off; off >>= 1)
        lsum += __shfl_down_sync(0xffffffffu, lsum, off);
    const int wid  = tid >> 5;
    const int lane = tid & 31;
    if (lane == 0) wsum[wid] = lsum;
    __syncthreads();

    const int bid = blockIdx.y * gridDim.x + blockIdx.x;
    if (tid < 32) {
        float v2 = (tid < TPB / 32) ? wsum[tid] : 0.0f;
#pragma unroll
        for (int off = 4; off; off >>= 1)
            v2 += __shfl_down_sync(0xffffffffu, v2, off);
        if (tid == 0) {
            g_part[bid] = v2;
            __threadfence();
            unsigned int old = atomicInc(&g_cnt, NBLK - 1u);
            isLast = (old == NBLK - 1u) ? 1 : 0;
        }
    }
    __syncthreads();

    // ---- last block reduces all partials ----
    if (isLast) {
        double ds = 0.0;
        for (int k = tid; k < NBLK; k += TPB)
            ds += (double)g_part[k];
#pragma unroll
        for (int off = 16; off; off >>= 1)
            ds += __shfl_down_sync(0xffffffffu, ds, off);
        if (lane == 0) dsh[wid] = ds;
        __syncthreads();
        if (tid == 0) {
            double tot = 0.0;
#pragma unroll
            for (int i = 0; i < TPB / 32; i++) tot += dsh[i];
            out[0] = (float)(tot / (double)((long long)NROWS * TT));
        }
    }
}

extern "C" void kernel_launch(void* const* d_in, const int* in_sizes, int n_in,
                              void* d_out, int out_size) {
    (void)in_sizes; (void)n_in; (void)out_size;
    const float* pred = (const float*)d_in[0];
    const float* tgt  = (const float*)d_in[1];
    dim3 grid(NTILES, NROWS);
    ssim_k<<<grid, TPB>>>(pred, tgt, (float*)d_out);
}

// round 5
// speedup vs baseline: 1.1048x; 1.0522x over previous
#include <cuda_runtime.h>

// SSIM 1-D loss, window 11, sigma 1.5, zero pad 5. B=16,C=32,T=48000 -> 512 rows.
// grid (24, 512), 256 threads/block, 8 outputs/thread (tile 2048).
// SMEM stages ONLY packed (u, v) as 64-bit, u=p+t, v=p-t (halved L1 bytes);
// (u^2, v^2) recomputed per window load with one fma.rn.f32x2.
// Conv: 18 sliding LDS.64 per thread, 22+2.25 packed fma per output.
// Block partial -> g_part; last block (atomicInc, self-resetting) reduces.

#define TT     48000
#define NROWS  512
#define TILE   2048
#define TPB    256
#define RPT    8
#define NTILES 24
#define NBLK   (NTILES * NROWS)
#define NL     (TILE + 16)                 // logical [tileStart-8, tileStart+TILE+8)
#define SSZ    (NL + (NL >> 3) + 2)        // pad: phys = i + (i>>3)
#define C1F    1.0e-4f
#define C2F    9.0e-4f
#define CCF    (C1F + C2F)

__device__ float g_part[NBLK];
__device__ unsigned int g_cnt = 0;         // self-resetting via atomicInc wrap

__device__ __forceinline__ unsigned long long pk2(float lo, float hi) {
    unsigned long long r;
    asm("mov.b64 %0, {%1, %2};" : "=l"(r) : "f"(lo), "f"(hi));
    return r;
}
__device__ __forceinline__ void upk2(unsigned long long v, float& lo, float& hi) {
    asm("mov.b64 {%0, %1}, %2;" : "=f"(lo), "=f"(hi) : "l"(v));
}
__device__ __forceinline__ unsigned long long ffma2(unsigned long long a,
                                                    unsigned long long b,
                                                    unsigned long long c) {
    unsigned long long d;
    asm("fma.rn.f32x2 %0, %1, %2, %3;" : "=l"(d) : "l"(a), "l"(b), "l"(c));
    return d;
}

__global__ __launch_bounds__(TPB) void ssim_k(const float* __restrict__ pred,
                                              const float* __restrict__ tgt,
                                              float* __restrict__ out) {
    __shared__ unsigned long long sUV[SSZ];    // packed (u, v) only
    __shared__ float  wsum[TPB / 32];
    __shared__ double dsh[TPB / 32];
    __shared__ int    isLast;

    const int tid       = threadIdx.x;
    const int tile      = blockIdx.x;
    const int row       = blockIdx.y;
    const int rowBase   = row * TT;
    const int tileStart = tile * TILE;

    // ---- interior: 8 elems/thread, 2x float4 loads (TT % 8 == 0) ----
    {
        const int src0 = tileStart + tid * RPT;
        float p[RPT], t[RPT];
        if (src0 + RPT - 1 < TT) {
            const float4* pp = reinterpret_cast<const float4*>(pred + rowBase + src0);
            const float4* tp = reinterpret_cast<const float4*>(tgt  + rowBase + src0);
            float4 pa = pp[0], pb = pp[1];
            float4 ta = tp[0], tb = tp[1];
            p[0]=pa.x; p[1]=pa.y; p[2]=pa.z; p[3]=pa.w;
            p[4]=pb.x; p[5]=pb.y; p[6]=pb.z; p[7]=pb.w;
            t[0]=ta.x; t[1]=ta.y; t[2]=ta.z; t[3]=ta.w;
            t[4]=tb.x; t[5]=tb.y; t[6]=tb.z; t[7]=tb.w;
        } else {
#pragma unroll
            for (int e = 0; e < RPT; e++) { p[e] = 0.f; t[e] = 0.f; }
        }
        // logical i0 = 8 + tid*8 (multiple of 8) -> phys base = 9*(tid+1)
        const int ph0 = 9 * (tid + 1);
#pragma unroll
        for (int e = 0; e < RPT; e++) {
            sUV[ph0 + e] = pk2(p[e] + t[e], p[e] - t[e]);
        }
    }
    // ---- halos: logical 0..7 (phys == i) and 2056..2063 (phys = i+257) ----
    if (tid < 8) {
        int src = tileStart - 8 + tid;
        float p = 0.f, t = 0.f;
        if (src >= 0) { p = pred[rowBase + src]; t = tgt[rowBase + src]; }
        sUV[tid] = pk2(p + t, p - t);
    } else if (tid >= 32 && tid < 40) {
        int h = tid - 32;
        int src = tileStart + TILE + h;
        float p = 0.f, t = 0.f;
        if (src < TT) { p = pred[rowBase + src]; t = tgt[rowBase + src]; }
        sUV[2056 + h + 257] = pk2(p + t, p - t);
    }
    __syncthreads();

    // ---- packed Gaussian weights ----
    const float Wv[11] = {
        0.001028380f, 0.007598758f, 0.036000773f, 0.109360755f, 0.213005542f,
        0.266011585f,
        0.213005542f, 0.109360755f, 0.036000773f, 0.007598758f, 0.001028380f
    };
    unsigned long long wp[11];
#pragma unroll
    for (int w = 0; w < 11; w++) wp[w] = pk2(Wv[w], Wv[w]);

    // ---- sliding-window conv: 18 LDS.64, squares on the fly, 194 FFMA2 ----
    unsigned long long aUV[RPT], aPQ[RPT];
#pragma unroll
    for (int j = 0; j < RPT; j++) { aUV[j] = 0ull; aPQ[j] = 0ull; }

    const int s = tid * RPT + 3;               // first logical read index
#pragma unroll
    for (int k = 0; k < RPT + 10; k++) {
        int li = s + k;
        unsigned long long quv = sUV[li + (li >> 3)];
        unsigned long long qpq = ffma2(quv, quv, 0ull);   // (u^2, v^2)
#pragma unroll
        for (int j = 0; j < RPT; j++) {
            int w = k - j;
            if (w >= 0 && w < 11) {
                aUV[j] = ffma2(quv, wp[w], aUV[j]);
                aPQ[j] = ffma2(qpq, wp[w], aPQ[j]);
            }
        }
    }

    // ---- epilogue: accumulate ssim (validity-predicated) ----
    float ssum = 0.0f;
    const int o0 = tileStart + tid * RPT;
#pragma unroll
    for (int j = 0; j < RPT; j++) {
        unsigned long long s2 = ffma2(aUV[j], aUV[j], 0ull);
        float U2, V2; upk2(s2, U2, V2);
        float Pu, Pv; upk2(aPQ[j], Pu, Pv);
        float t1 = fmaf(0.5f, U2, C1F);
        float a2 = fmaf(-0.5f, V2, t1);        // (U2-V2)/2 + C1
        float b2 = fmaf( 0.5f, V2, t1);        // (U2+V2)/2 + C1
        float c2 = fmaf(0.5f, Pu, fmaf(-0.5f, Pv, CCF - a2));
        float d2 = fmaf(0.5f, Pu, fmaf( 0.5f, Pv, CCF - b2));
        float ssim = __fdividef(a2 * c2, b2 * d2);
        if (o0 + j < TT) ssum += ssim;
    }
    int vc = TT - o0;
    vc = vc < 0 ? 0 : (vc > RPT ? RPT : vc);
    float lsum = (float)vc - ssum;

    // ---- block reduce ----
#pragma unroll
    for (int off = 16; off; off >>= 1)
        lsum += __shfl_down_sync(0xffffffffu, lsum, off);
    const int wid  = tid >> 5;
    const int lane = tid & 31;
    if (lane == 0) wsum[wid] = lsum;
    __syncthreads();

    const int bid = blockIdx.y * gridDim.x + blockIdx.x;
    if (tid < 32) {
        float v2 = (tid < TPB / 32) ? wsum[tid] : 0.0f;
#pragma unroll
        for (int off = 4; off; off >>= 1)
            v2 += __shfl_down_sync(0xffffffffu, v2, off);
        if (tid == 0) {
            g_part[bid] = v2;
            __threadfence();
            unsigned int old = atomicInc(&g_cnt, NBLK - 1u);
            isLast = (old == NBLK - 1u) ? 1 : 0;
        }
    }
    __syncthreads();

    // ---- last block reduces all partials ----
    if (isLast) {
        double ds = 0.0;
        for (int k = tid; k < NBLK; k += TPB)
            ds += (double)g_part[k];
#pragma unroll
        for (int off = 16; off; off >>= 1)
            ds += __shfl_down_sync(0xffffffffu, ds, off);
        if (lane == 0) dsh[wid] = ds;
        __syncthreads();
        if (tid == 0) {
            double tot = 0.0;
#pragma unroll
            for (int i = 0; i < TPB / 32; i++) tot += dsh[i];
            out[0] = (float)(tot / (double)((long long)NROWS * TT));
        }
    }
}

extern "C" void kernel_launch(void* const* d_in, const int* in_sizes, int n_in,
                              void* d_out, int out_size) {
    (void)in_sizes; (void)n_in; (void)out_size;
    const float* pred = (const float*)d_in[0];
    const float* tgt  = (const float*)d_in[1];
    dim3 grid(NTILES, NROWS);
    ssim_k<<<grid, TPB>>>(pred, tgt, (float*)d_out);
}

// round 7
// speedup vs baseline: 1.1662x; 1.0555x over previous
#include <cuda_runtime.h>

// SSIM 1-D loss, window 11, sigma 1.5, zero pad 5. B=16,C=32,T=48000 -> 512 rows.
// grid (24, 512), 256 threads/block, 8 outputs/thread (tile 2048).
// SMEM stages only packed (u, v), u=p+t, v=p-t; squares recomputed on the fly.
// Conv: 18 sliding LDS.64/thread, fma.rn.f32x2 throughout.
// Epilogue: SSIM math packed f32x2 across output pairs; scalar fast-divide.
// Block partial -> g_part; last block (atomicInc, self-resetting) reduces.

#define TT     48000
#define NROWS  512
#define TILE   2048
#define TPB    256
#define RPT    8
#define NTILES 24
#define NBLK   (NTILES * NROWS)
#define NL     (TILE + 16)                 // logical [tileStart-8, tileStart+TILE+8)
#define SSZ    (NL + (NL >> 3) + 2)        // pad: phys = i + (i>>3)
#define C1F    1.0e-4f
#define C2F    9.0e-4f
#define CCF    (C1F + C2F)

__device__ float g_part[NBLK];
__device__ unsigned int g_cnt = 0;         // self-resetting via atomicInc wrap

__device__ __forceinline__ unsigned long long pk2(float lo, float hi) {
    unsigned long long r;
    asm("mov.b64 %0, {%1, %2};" : "=l"(r) : "f"(lo), "f"(hi));
    return r;
}
__device__ __forceinline__ void upk2(unsigned long long v, float& lo, float& hi) {
    asm("mov.b64 {%0, %1}, %2;" : "=f"(lo), "=f"(hi) : "l"(v));
}
__device__ __forceinline__ unsigned long long ffma2(unsigned long long a,
                                                    unsigned long long b,
                                                    unsigned long long c) {
    unsigned long long d;
    asm("fma.rn.f32x2 %0, %1, %2, %3;" : "=l"(d) : "l"(a), "l"(b), "l"(c));
    return d;
}

__global__ __launch_bounds__(TPB, 6) void ssim_k(const float* __restrict__ pred,
                                                 const float* __restrict__ tgt,
                                                 float* __restrict__ out) {
    __shared__ unsigned long long sUV[SSZ];    // packed (u, v) only
    __shared__ float  wsum[TPB / 32];
    __shared__ double dsh[TPB / 32];
    __shared__ int    isLast;

    const int tid       = threadIdx.x;
    const int tile      = blockIdx.x;
    const int row       = blockIdx.y;
    const int rowBase   = row * TT;
    const int tileStart = tile * TILE;

    // ---- interior: 8 elems/thread, 2x float4 loads (TT % 8 == 0) ----
    {
        const int src0 = tileStart + tid * RPT;
        float p[RPT], t[RPT];
        if (src0 + RPT - 1 < TT) {
            const float4* pp = reinterpret_cast<const float4*>(pred + rowBase + src0);
            const float4* tp = reinterpret_cast<const float4*>(tgt  + rowBase + src0);
            float4 pa = pp[0], pb = pp[1];
            float4 ta = tp[0], tb = tp[1];
            p[0]=pa.x; p[1]=pa.y; p[2]=pa.z; p[3]=pa.w;
            p[4]=pb.x; p[5]=pb.y; p[6]=pb.z; p[7]=pb.w;
            t[0]=ta.x; t[1]=ta.y; t[2]=ta.z; t[3]=ta.w;
            t[4]=tb.x; t[5]=tb.y; t[6]=tb.z; t[7]=tb.w;
        } else {
#pragma unroll
            for (int e = 0; e < RPT; e++) { p[e] = 0.f; t[e] = 0.f; }
        }
        // logical i0 = 8 + tid*8 (multiple of 8) -> phys base = 9*(tid+1)
        const int ph0 = 9 * (tid + 1);
#pragma unroll
        for (int e = 0; e < RPT; e++) {
            sUV[ph0 + e] = pk2(p[e] + t[e], p[e] - t[e]);
        }
    }
    // ---- halos: logical 0..7 (phys == i) and 2056..2063 (phys = i+257) ----
    if (tid < 8) {
        int src = tileStart - 8 + tid;
        float p = 0.f, t = 0.f;
        if (src >= 0) { p = pred[rowBase + src]; t = tgt[rowBase + src]; }
        sUV[tid] = pk2(p + t, p - t);
    } else if (tid >= 32 && tid < 40) {
        int h = tid - 32;
        int src = tileStart + TILE + h;
        float p = 0.f, t = 0.f;
        if (src < TT) { p = pred[rowBase + src]; t = tgt[rowBase + src]; }
        sUV[2056 + h + 257] = pk2(p + t, p - t);
    }
    __syncthreads();

    // ---- packed Gaussian weights ----
    const float Wv[11] = {
        0.001028380f, 0.007598758f, 0.036000773f, 0.109360755f, 0.213005542f,
        0.266011585f,
        0.213005542f, 0.109360755f, 0.036000773f, 0.007598758f, 0.001028380f
    };
    unsigned long long wp[11];
#pragma unroll
    for (int w = 0; w < 11; w++) wp[w] = pk2(Wv[w], Wv[w]);

    // ---- sliding-window conv: 18 LDS.64, squares on the fly ----
    unsigned long long aUV[RPT], aPQ[RPT];
#pragma unroll
    for (int j = 0; j < RPT; j++) { aUV[j] = 0ull; aPQ[j] = 0ull; }

    const int s = tid * RPT + 3;               // first logical read index
#pragma unroll
    for (int k = 0; k < RPT + 10; k++) {
        int li = s + k;
        unsigned long long quv = sUV[li + (li >> 3)];
        unsigned long long qpq = ffma2(quv, quv, 0ull);   // (u^2, v^2)
#pragma unroll
        for (int j = 0; j < RPT; j++) {
            int w = k - j;
            if (w >= 0 && w < 11) {
                aUV[j] = ffma2(quv, wp[w], aUV[j]);
                aPQ[j] = ffma2(qpq, wp[w], aPQ[j]);
            }
        }
    }

    // ---- epilogue: packed f32x2 SSIM across output pairs ----
    const unsigned long long halfp  = pk2( 0.5f,  0.5f);
    const unsigned long long nhalfp = pk2(-0.5f, -0.5f);
    const unsigned long long nonep  = pk2(-1.0f, -1.0f);
    const unsigned long long c1p    = pk2(C1F, C1F);
    const unsigned long long ccp    = pk2(CCF, CCF);

    float ssum = 0.0f;
    const int o0 = tileStart + tid * RPT;
#pragma unroll
    for (int jp = 0; jp < RPT; jp += 2) {
        float U0, V0, U1, V1, P0, Q0, P1, Q1;
        upk2(aUV[jp],     U0, V0);
        upk2(aUV[jp + 1], U1, V1);
        upk2(aPQ[jp],     P0, Q0);
        upk2(aPQ[jp + 1], P1, Q1);
        unsigned long long UU = pk2(U0, U1), VV = pk2(V0, V1);
        unsigned long long PP = pk2(P0, P1), QQ = pk2(Q0, Q1);

        unsigned long long U2 = ffma2(UU, UU, 0ull);
        unsigned long long V2 = ffma2(VV, VV, 0ull);
        unsigned long long t1 = ffma2(U2, halfp,  c1p);   // U2/2 + C1
        unsigned long long a2 = ffma2(V2, nhalfp, t1);    // (U2-V2)/2 + C1
        unsigned long long b2 = ffma2(V2, halfp,  t1);    // (U2+V2)/2 + C1
        unsigned long long c2 = ffma2(PP, halfp,
                                 ffma2(QQ, nhalfp, ffma2(a2, nonep, ccp)));
        unsigned long long d2 = ffma2(PP, halfp,
                                 ffma2(QQ, halfp,  ffma2(b2, nonep, ccp)));
        unsigned long long num = ffma2(a2, c2, 0ull);
        unsigned long long den = ffma2(b2, d2, 0ull);

        float n0, n1, e0, e1;
        upk2(num, n0, n1);
        upk2(den, e0, e1);
        float s0 = __fdividef(n0, e0);
        float s1 = __fdividef(n1, e1);
        if (o0 + jp     < TT) ssum += s0;
        if (o0 + jp + 1 < TT) ssum += s1;
    }
    int vc = TT - o0;
    vc = vc < 0 ? 0 : (vc > RPT ? RPT : vc);
    float lsum = (float)vc - ssum;

    // ---- block reduce ----
#pragma unroll
    for (int off = 16; off; off >>= 1)
        lsum += __shfl_down_sync(0xffffffffu, lsum, off);
    const int wid  = tid >> 5;
    const int lane = tid & 31;
    if (lane == 0) wsum[wid] = lsum;
    __syncthreads();

    const int bid = blockIdx.y * gridDim.x + blockIdx.x;
    if (tid < 32) {
        float v2 = (tid < TPB / 32) ? wsum[tid] : 0.0f;
#pragma unroll
        for (int off = 4; off; off >>= 1)
            v2 += __shfl_down_sync(0xffffffffu, v2, off);
        if (tid == 0) {
            g_part[bid] = v2;
            __threadfence();
            unsigned int old = atomicInc(&g_cnt, NBLK - 1u);
            isLast = (old == NBLK - 1u) ? 1 : 0;
        }
    }
    __syncthreads();

    // ---- last block reduces all partials ----
    if (isLast) {
        double ds = 0.0;
        for (int k = tid; k < NBLK; k += TPB)
            ds += (double)g_part[k];
#pragma unroll
        for (int off = 16; off; off >>= 1)
            ds += __shfl_down_sync(0xffffffffu, ds, off);
        if (lane == 0) dsh[wid] = ds;
        __syncthreads();
        if (tid == 0) {
            double tot = 0.0;
#pragma unroll
            for (int i = 0; i < TPB / 32; i++) tot += dsh[i];
            out[0] = (float)(tot / (double)((long long)NROWS * TT));
        }
    }
}

extern "C" void kernel_launch(void* const* d_in, const int* in_sizes, int n_in,
                              void* d_out, int out_size) {
    (void)in_sizes; (void)n_in; (void)out_size;
    const float* pred = (const float*)d_in[0];
    const float* tgt  = (const float*)d_in[1];
    dim3 grid(NTILES, NROWS);
    ssim_k<<<grid, TPB>>>(pred, tgt, (float*)d_out);
}